// round 1
// baseline (speedup 1.0000x reference)
#include <cuda_runtime.h>
#include <cstdint>

// Problem constants (fixed shapes from reference)
#define M_TOTAL 8192      // 4 * 2048
#define N_TOTAL 4096
#define K_TOTAL 4096

#define BM 128
#define BN 128
#define BK 32
#define S_STRIDE 36       // BK + 4 pad (floats); 36*4=144 bytes, 16B-aligned per row

// Scratch: TF32(RNA)-rounded copies of A and W*mask. __device__ globals (no alloc).
__device__ float g_A[(size_t)M_TOTAL * K_TOTAL];   // 134 MB
__device__ float g_WB[(size_t)N_TOTAL * K_TOTAL];  // 67 MB

__device__ __forceinline__ float tf32_rna(float x) {
    unsigned u;
    asm("cvt.rna.tf32.f32 %0, %1;" : "=r"(u) : "f"(x));
    return __uint_as_float(u);
}

__global__ void prep_w_kernel(const float4* __restrict__ w,
                              const float4* __restrict__ m, int n4) {
    int i = blockIdx.x * blockDim.x + threadIdx.x;
    if (i >= n4) return;
    float4 a = w[i], b = m[i], r;
    r.x = tf32_rna(a.x * b.x);
    r.y = tf32_rna(a.y * b.y);
    r.z = tf32_rna(a.z * b.z);
    r.w = tf32_rna(a.w * b.w);
    reinterpret_cast<float4*>(g_WB)[i] = r;
}

__global__ void prep_a_kernel(const float4* __restrict__ a, int n4) {
    int i = blockIdx.x * blockDim.x + threadIdx.x;
    if (i >= n4) return;
    float4 v = a[i], r;
    r.x = tf32_rna(v.x);
    r.y = tf32_rna(v.y);
    r.z = tf32_rna(v.z);
    r.w = tf32_rna(v.w);
    reinterpret_cast<float4*>(g_A)[i] = r;
}

__device__ __forceinline__ void cp_async16(void* dst, const void* src) {
    unsigned sdst = (unsigned)__cvta_generic_to_shared(dst);
    asm volatile("cp.async.cg.shared.global [%0], [%1], 16;" :: "r"(sdst), "l"(src));
}

__device__ __forceinline__ void mma_tf32(float* c, const unsigned* a, const unsigned* b) {
    asm volatile(
        "mma.sync.aligned.m16n8k8.row.col.f32.tf32.tf32.f32 "
        "{%0,%1,%2,%3}, {%4,%5,%6,%7}, {%8,%9}, {%0,%1,%2,%3};"
        : "+f"(c[0]), "+f"(c[1]), "+f"(c[2]), "+f"(c[3])
        : "r"(a[0]), "r"(a[1]), "r"(a[2]), "r"(a[3]),
          "r"(b[0]), "r"(b[1]));
}

__global__ __launch_bounds__(256)
void gemm_tf32_kernel(float* __restrict__ out, const float* __restrict__ bias) {
    extern __shared__ float smem[];
    float* As = smem;                      // [2][BM][S_STRIDE]
    float* Bs = smem + 2 * BM * S_STRIDE;  // [2][BN][S_STRIDE]

    const int tid  = threadIdx.x;
    const int wid  = tid >> 5;
    const int lane = tid & 31;
    const int g    = lane >> 2;   // group id 0..7
    const int t4   = lane & 3;    // 0..3

    const int warp_m = (wid >> 2) * 64;  // 0 or 64
    const int warp_n = (wid & 3) * 32;   // 0,32,64,96

    const int bm = blockIdx.y * BM;
    const int bn = blockIdx.x * BN;

    const float* Abase = g_A  + (size_t)bm * K_TOTAL;
    const float* Bbase = g_WB + (size_t)bn * K_TOTAL;

    float acc[4][4][4];
    #pragma unroll
    for (int i = 0; i < 4; i++)
        #pragma unroll
        for (int j = 0; j < 4; j++)
            #pragma unroll
            for (int r = 0; r < 4; r++) acc[i][j][r] = 0.0f;

    // Tile loader: 1024 float4 per operand tile, 4 per thread.
    auto load_tile = [&](int kt, int buf) {
        const int k0 = kt * BK;
        #pragma unroll
        for (int i = 0; i < 4; i++) {
            int idx = tid + i * 256;
            int row = idx >> 3;
            int c4  = (idx & 7) * 4;
            cp_async16(&As[buf * BM * S_STRIDE + row * S_STRIDE + c4],
                       Abase + (size_t)row * K_TOTAL + k0 + c4);
            cp_async16(&Bs[buf * BM * S_STRIDE + row * S_STRIDE + c4],
                       Bbase + (size_t)row * K_TOTAL + k0 + c4);
        }
        asm volatile("cp.async.commit_group;");
    };

    load_tile(0, 0);

    const int KT = K_TOTAL / BK;  // 128
    for (int kt = 0; kt < KT; ++kt) {
        asm volatile("cp.async.wait_group 0;");
        __syncthreads();
        const int buf = kt & 1;
        if (kt + 1 < KT) load_tile(kt + 1, buf ^ 1);

        const float* Ab = &As[buf * BM * S_STRIDE];
        const float* Bb = &Bs[buf * BM * S_STRIDE];

        #pragma unroll
        for (int ks = 0; ks < 4; ++ks) {
            const int k0 = ks * 8;
            unsigned a[4][4], b[4][2];
            #pragma unroll
            for (int i = 0; i < 4; i++) {
                const float* ap = Ab + (warp_m + i * 16) * S_STRIDE + k0;
                a[i][0] = __float_as_uint(ap[g * S_STRIDE + t4]);
                a[i][1] = __float_as_uint(ap[(g + 8) * S_STRIDE + t4]);
                a[i][2] = __float_as_uint(ap[g * S_STRIDE + t4 + 4]);
                a[i][3] = __float_as_uint(ap[(g + 8) * S_STRIDE + t4 + 4]);
            }
            #pragma unroll
            for (int j = 0; j < 4; j++) {
                const float* bp = Bb + (warp_n + j * 8) * S_STRIDE + k0;
                b[j][0] = __float_as_uint(bp[g * S_STRIDE + t4]);
                b[j][1] = __float_as_uint(bp[g * S_STRIDE + t4 + 4]);
            }
            #pragma unroll
            for (int i = 0; i < 4; i++)
                #pragma unroll
                for (int j = 0; j < 4; j++)
                    mma_tf32(acc[i][j], a[i], b[j]);
        }
        // No trailing sync needed: next iteration's top barrier protects the
        // buffer being overwritten two iterations out.
    }

    // Epilogue: fragment c layout for m16n8k8: c0 @ (g, t4*2), c1 @ (g, t4*2+1),
    // c2/c3 @ row g+8. float2 stores, bias fused.
    const int row0 = bm + warp_m;
    const int col0 = bn + warp_n;
    #pragma unroll
    for (int i = 0; i < 4; i++) {
        #pragma unroll
        for (int j = 0; j < 4; j++) {
            int r = row0 + i * 16 + g;
            int c = col0 + j * 8 + t4 * 2;
            float b0 = bias[c], b1 = bias[c + 1];
            float2 v0 = make_float2(acc[i][j][0] + b0, acc[i][j][1] + b1);
            float2 v1 = make_float2(acc[i][j][2] + b0, acc[i][j][3] + b1);
            *reinterpret_cast<float2*>(out + (size_t)r * N_TOTAL + c) = v0;
            *reinterpret_cast<float2*>(out + (size_t)(r + 8) * N_TOTAL + c) = v1;
        }
    }
}

extern "C" void kernel_launch(void* const* d_in, const int* in_sizes, int n_in,
                              void* d_out, int out_size) {
    const float* data   = (const float*)d_in[0];  // [4,2048,4096]
    const float* weight = (const float*)d_in[1];  // [4096,4096]
    const float* w_mask = (const float*)d_in[2];  // [4096,4096]
    const float* bias_p = (const float*)d_in[3];  // [4096]
    float* out = (float*)d_out;

    // TF32(RNA) pre-rounding into device scratch
    {
        int n4 = (N_TOTAL * K_TOTAL) / 4;
        prep_w_kernel<<<(n4 + 255) / 256, 256>>>(
            (const float4*)weight, (const float4*)w_mask, n4);
    }
    {
        int n4 = (M_TOTAL * K_TOTAL) / 4;
        prep_a_kernel<<<(n4 + 255) / 256, 256>>>((const float4*)data, n4);
    }

    // GEMM
    const int smem_bytes = 2 * (BM + BN) * S_STRIDE * sizeof(float);  // 73728
    cudaFuncSetAttribute(gemm_tf32_kernel,
                         cudaFuncAttributeMaxDynamicSharedMemorySize, smem_bytes);
    dim3 grid(N_TOTAL / BN, M_TOTAL / BM);  // (32, 64)
    gemm_tf32_kernel<<<grid, 256, smem_bytes>>>(out, bias_p);
}